// round 16
// baseline (speedup 1.0000x reference)
#include <cuda_runtime.h>
#include <cuda_bf16.h>
#include <math.h>
#include <stdint.h>

#define SLOPE 0.01f
constexpr float RCOEF = 1.0f - SLOPE;
#define TAU 0.01f

// -------- problem constants --------
constexpr int Dd    = 32;
constexpr int Hh    = 128;
constexpr int Bb    = 64;
constexpr int Tt    = 514;
constexpr int TTt   = 512;
constexpr int NTOT  = Bb * TTt;          // 32768
constexpr int NTILE = 128;
constexpr int NTILES = NTOT / NTILE;     // 256

// output layout (reference return order, concatenated)
constexpr size_t RES_OFF  = 0;                        // (64,512,32)
constexpr size_t SUM_OFF  = (size_t)Bb * TTt * Dd;    // (64,)
constexpr size_t HIST_OFF = SUM_OFF + Bb;             // (32,32768,1,64)

// -------- shared offsets (u32 units) — 67.7 KB, 3 CTAs/SM --------
constexpr int XWS = 36;                  // x-window row stride
constexpr int W1S = 68;                  // W1 row stride (row-major h x k)
constexpr int O_XW    = 0;                               // 130*36 = 4680 (reused as u_hi later)
constexpr int O_W1    = 4680;                            // 128*68 = 8704 (reused as u_lo later)
constexpr int O_MASK  = 13384;                           // 128*4
constexpr int O_S     = 13896;                           // 64
constexpr int O_WBW   = 13960;                           // 128*4: {w1last, b1, w2, pad}
constexpr int O_YY    = 14472;                           // 132
constexpr int O_RS    = 14604;                           // 128
constexpr int O_JS    = 14732;                           // 128
constexpr int O_RED   = 14860;                           // 1
constexpr int O_QCNT  = 14861;                           // 1 (+2 pad)
constexpr int O_QBUF  = 14864;                           // 2048
constexpr int QCAP    = 2048;
constexpr int SMEM_U32 = O_QBUF + QCAP;                  // 16912
constexpr int SMEM_BYTES = SMEM_U32 * 4;                 // 67648

// u_* packed arrays (reusing dead regions): [k'=0..63][h_pair=0..63], stride 68
constexpr int O_UH = O_XW;    // 4352 <= 4680
constexpr int O_UL = O_W1;    // 4352 <= 8704
constexpr int UST  = 68;

__device__ __forceinline__ uint32_t f2tf32(float f) {
    uint32_t u;
    asm("cvt.rna.tf32.f32 %0, %1;" : "=r"(u) : "f"(f));
    return u;
}

__device__ __forceinline__ void mma8(float* d, const uint32_t* a, uint32_t b0, uint32_t b1) {
    asm volatile(
        "mma.sync.aligned.m16n8k8.row.col.f32.tf32.tf32.f32 "
        "{%0,%1,%2,%3}, {%4,%5,%6,%7}, {%8,%9}, {%0,%1,%2,%3};"
        : "+f"(d[0]), "+f"(d[1]), "+f"(d[2]), "+f"(d[3])
        : "r"(a[0]), "r"(a[1]), "r"(a[2]), "r"(a[3]), "r"(b0), "r"(b1));
}
__device__ __forceinline__ void mma16bf(float* d, const uint32_t* a, uint32_t b0, uint32_t b1) {
    asm volatile(
        "mma.sync.aligned.m16n8k16.row.col.f32.bf16.bf16.f32 "
        "{%0,%1,%2,%3}, {%4,%5,%6,%7}, {%8,%9}, {%0,%1,%2,%3};"
        : "+f"(d[0]), "+f"(d[1]), "+f"(d[2]), "+f"(d[3])
        : "r"(a[0]), "r"(a[1]), "r"(a[2]), "r"(a[3]), "r"(b0), "r"(b1));
}

// 2 mask bits -> bf16x2 {1.0|0.0, 1.0|0.0}; low half = lower h (bit0)
__device__ __forceinline__ uint32_t mask2bf(uint32_t p) {
    return (p & 1u) * 0x3F80u | (p & 2u) * 0x1FC00000u;
}

__global__ void zero_sum_kernel(float* out) { out[SUM_OFF + threadIdx.x] = 0.0f; }

extern __shared__ uint32_t smemu[];

__global__ __launch_bounds__(256, 3)
void fused_mma(const float* __restrict__ x,  const float* __restrict__ W1,
               const float* __restrict__ b1, const float* __restrict__ W2,
               const float* __restrict__ b2, float* __restrict__ out)
{
    float* sf = (float*)smemu;
    const int tid  = threadIdx.x;
    const int lane = tid & 31;
    const int w    = tid >> 5;
    const int lr   = lane >> 2;   // 0..7
    const int lc   = lane & 3;    // 0..3

    const int d  = blockIdx.x;
    const int n0 = blockIdx.y * NTILE;
    const int bb = n0 / TTt;
    const int t0 = n0 % TTt;

    // ---------------- preamble ----------------
    {
        const float* W1g = W1 + (size_t)d * Hh * 65;
        for (int idx = tid; idx < Hh * 65; idx += 256) {
            int h = idx / 65;
            int k = idx - h * 65;
            float v = W1g[idx];
            if (k == 64) sf[O_WBW + 4 * h] = v;       // w1last
            else         sf[O_W1 + h * W1S + k] = v;
        }
        const float* xg = x + ((size_t)bb * Tt + t0) * Dd;
        for (int idx = tid; idx < 130 * 32; idx += 256) {
            int r = idx >> 5, c = idx & 31;
            float v = xg[idx];
            sf[O_XW + r * XWS + c] = v;
            if (c == d) sf[O_YY + r] = v;
        }
        if (tid < 128) {
            sf[O_WBW + 4 * tid + 1] = b1[(size_t)d * Hh + tid];
            sf[O_WBW + 4 * tid + 2] = W2[(size_t)d * Hh + tid];
            sf[O_RS + tid] = 0.0f;
            sf[O_JS + tid] = 0.0f;
        }
        if (tid == 0) { sf[O_RED] = 0.0f; smemu[O_QCNT] = 0u; }
    }
    __syncthreads();

    // colsums S[k] = sum_h w2[h]*W1[h][k]
    if (tid < 64) {
        float s = 0.0f;
        #pragma unroll 8
        for (int h = 0; h < Hh; h++)
            s = fmaf(sf[O_WBW + 4 * h + 2], sf[O_W1 + h * W1S + tid], s);
        sf[O_S + tid] = s;
    }

    // ---------------- GEMM A: pre ~= XX @ W1[:, :64]^T  (1xTF32 rna) ----------------
    // warp tile 32n x 64h, split along h into two 32n x 32h passes (acc 32 regs)
    const int nblk = (w & 3) * 32;
    const int hgrp = (w >> 2);     // 0 or 1

    float rp[2][2] = {{0.0f, 0.0f}, {0.0f, 0.0f}};
    float jp[2][2] = {{0.0f, 0.0f}, {0.0f, 0.0f}};

    #pragma unroll 1
    for (int pass = 0; pass < 2; pass++) {
        const int hb = hgrp * 64 + pass * 32;

        float acc[2][4][4];
        #pragma unroll
        for (int i = 0; i < 2; i++)
            #pragma unroll
            for (int j = 0; j < 4; j++)
                #pragma unroll
                for (int q = 0; q < 4; q++) acc[i][j][q] = 0.0f;

        #pragma unroll 2
        for (int s = 0; s < 8; s++) {
            const int l  = s >> 2;
            const int c0 = ((8 * s) & 31) + lc;
            uint32_t a[2][4];
            #pragma unroll
            for (int i = 0; i < 2; i++) {
                int base = O_XW + (nblk + 16 * i + lr + l) * XWS + c0;
                a[i][0] = f2tf32(sf[base]);
                a[i][1] = f2tf32(sf[base + 8 * XWS]);
                a[i][2] = f2tf32(sf[base + 4]);
                a[i][3] = f2tf32(sf[base + 8 * XWS + 4]);
            }
            #pragma unroll
            for (int j = 0; j < 4; j++) {
                int hrow = O_W1 + (hb + 8 * j + lr) * W1S + 8 * s + lc;
                uint32_t b0 = f2tf32(sf[hrow]);
                uint32_t b1v = f2tf32(sf[hrow + 4]);
                #pragma unroll
                for (int i = 0; i < 2; i++)
                    mma8(acc[i][j], a[i], b0, b1v);
            }
        }

        // epilogue for this h-pass: mask (approx sign), rp/jp partials, branchless queue bits
        #pragma unroll
        for (int i = 0; i < 2; i++) {
            #pragma unroll
            for (int ci = 0; ci < 2; ci++) {
                const int row = nblk + 16 * i + 8 * ci + lr;
                const float yyv = sf[O_YY + row + 2];
                uint32_t m = 0, um = 0;
                #pragma unroll
                for (int j = 0; j < 4; j++) {
                    #pragma unroll
                    for (int cj = 0; cj < 2; cj++) {
                        const int h = hb + 8 * j + 2 * lc + cj;
                        const float4 wbw = *(const float4*)&sf[O_WBW + 4 * h];
                        // wbw.x = w1last, wbw.y = b1, wbw.z = w2
                        float pre = fmaf(yyv, wbw.x, acc[i][j][2 * ci + cj]) + wbw.y;
                        float gv = (pre >= 0.0f) ? wbw.z : SLOPE * wbw.z;
                        rp[i][ci] = fmaf(pre, gv, rp[i][ci]);
                        jp[i][ci] = fmaf(gv, wbw.x, jp[i][ci]);
                        if (pre >= 0.0f) m |= 1u << (8 * j + 2 * lc + cj);
                        um |= (fabsf(pre) < TAU) ? (1u << (2 * j + cj)) : 0u;   // branchless
                    }
                }
                // rare push of uncertain entries (single guarded region, usually skipped)
                if (um) {
                    do {
                        const int b = __ffs(um) - 1;
                        um &= um - 1u;
                        const int h = hb + 8 * (b >> 1) + 2 * lc + (b & 1);
                        uint32_t qi = atomicAdd(&smemu[O_QCNT], 1u);
                        if (qi < QCAP) smemu[O_QBUF + qi] = (uint32_t)row | ((uint32_t)h << 16);
                    } while (um);
                }
                m |= __shfl_xor_sync(0xffffffffu, m, 1);
                m |= __shfl_xor_sync(0xffffffffu, m, 2);
                if (lc == 0)
                    smemu[O_MASK + row * 4 + 2 * hgrp + pass] = m;
            }
        }
    }

    // rp/jp reductions
    #pragma unroll
    for (int i = 0; i < 2; i++) {
        #pragma unroll
        for (int ci = 0; ci < 2; ci++) {
            const int row = nblk + 16 * i + 8 * ci + lr;
            float rpv = rp[i][ci], jpv = jp[i][ci];
            rpv += __shfl_xor_sync(0xffffffffu, rpv, 1);
            rpv += __shfl_xor_sync(0xffffffffu, rpv, 2);
            jpv += __shfl_xor_sync(0xffffffffu, jpv, 1);
            jpv += __shfl_xor_sync(0xffffffffu, jpv, 2);
            if (lc == 0) {
                atomicAdd(&sf[O_RS + row], rpv);
                atomicAdd(&sf[O_JS + row], jpv);
            }
        }
    }
    __syncthreads();

    // ---------------- fixup: warp-cooperative exact fp32 pre for uncertain entries -------
    {
        int qn = (int)smemu[O_QCNT];
        if (qn > QCAP) qn = QCAP;
        for (int q = w; q < qn; q += 8) {          // one queue entry per warp
            const uint32_t e = smemu[O_QBUF + q];
            const int row = (int)(e & 0xFFFFu);
            const int h   = (int)(e >> 16);
            // lanes: k = lane and k = lane + 32 (consecutive smem -> conflict-free)
            float acc = sf[O_XW + row * XWS + lane]       * sf[O_W1 + h * W1S + lane]
                      + sf[O_XW + (row + 1) * XWS + lane] * sf[O_W1 + h * W1S + lane + 32];
            #pragma unroll
            for (int o = 16; o; o >>= 1) acc += __shfl_xor_sync(0xffffffffu, acc, o);
            if (lane == 0) {
                const float4 wbw = *(const float4*)&sf[O_WBW + 4 * h];
                const float pre = acc + fmaf(sf[O_YY + row + 2], wbw.x, wbw.y);
                uint32_t* mw = &smemu[O_MASK + row * 4 + (h >> 5)];
                const uint32_t bit = 1u << (h & 31);
                const bool newb = (pre >= 0.0f);
                const bool oldb = ((*mw) & bit) != 0u;
                if (newb != oldb) {
                    atomicXor(mw, bit);
                    const float dg = (newb ? RCOEF : -RCOEF) * wbw.z;   // g_new - g_old
                    atomicAdd(&sf[O_JS + row], dg * wbw.x);
                    atomicAdd(&sf[O_RS + row], dg * pre);
                }
            }
        }
    }
    __syncthreads();

    // residual + logdet outputs (read corrected RS/JS)
    if (tid < 128) {
        const int n = tid;
        out[RES_OFF + ((size_t)(bb * TTt + t0 + n)) * Dd + d] = sf[O_RS + n] + __ldg(&b2[d]);
        float ls = logf(fabsf(sf[O_JS + n]));
        #pragma unroll
        for (int o = 16; o; o >>= 1) ls += __shfl_down_sync(0xffffffffu, ls, o);
        if (lane == 0) atomicAdd(&sf[O_RED], ls);
    }

    // ---------------- build u = w2 .* W1 as packed bf16 hi/lo --------------------
    uint32_t lo_st[16];
    #pragma unroll
    for (int t = 0; t < 16; t++) {
        const int idx = tid + 256 * t;          // 0..4095
        const int k = idx >> 6, hp = idx & 63;
        const int h0 = 2 * hp, h1 = 2 * hp + 1;
        const float u0 = sf[O_W1 + h0 * W1S + k] * sf[O_WBW + 4 * h0 + 2];
        const float u1 = sf[O_W1 + h1 * W1S + k] * sf[O_WBW + 4 * h1 + 2];
        __nv_bfloat162 hi2 = __floats2bfloat162_rn(u0, u1);   // .x (low) = even h
        smemu[O_UH + k * UST + hp] = *(uint32_t*)&hi2;        // x-window dead after fixup
        const float l0 = u0 - __bfloat162float(hi2.x);
        const float l1 = u1 - __bfloat162float(hi2.y);
        __nv_bfloat162 lo2 = __floats2bfloat162_rn(l0, l1);
        lo_st[t] = *(uint32_t*)&lo2;
    }
    __syncthreads();   // all W1 reads complete before overwrite
    #pragma unroll
    for (int t = 0; t < 16; t++) {
        const int idx = tid + 256 * t;
        const int k = idx >> 6, hp = idx & 63;
        smemu[O_UL + k * UST + hp] = lo_st[t];
    }
    __syncthreads();

    // ---------------- GEMM B: jac = SLOPE*S + RCOEF*(mask @ u)  (bf16 hi+lo, k16) -------
    const int nblk2 = (w & 3) * 32;
    const int kblk  = (w >> 2) * 32;

    float acc2[2][4][4];
    #pragma unroll
    for (int i = 0; i < 2; i++)
        #pragma unroll
        for (int j = 0; j < 4; j++)
            #pragma unroll
            for (int q = 0; q < 4; q++) acc2[i][j][q] = 0.0f;

    #pragma unroll 2
    for (int step = 0; step < 8; step++) {
        const int mw    = step >> 1;
        const int shift = (step & 1) * 16 + 2 * lc;
        uint32_t a[2][4];
        #pragma unroll
        for (int i = 0; i < 2; i++) {
            const uint32_t mLo = smemu[O_MASK + (nblk2 + 16 * i + lr) * 4 + mw];
            const uint32_t mHi = smemu[O_MASK + (nblk2 + 16 * i + lr + 8) * 4 + mw];
            a[i][0] = mask2bf((mLo >> shift) & 3u);
            a[i][1] = mask2bf((mHi >> shift) & 3u);
            a[i][2] = mask2bf((mLo >> (shift + 8)) & 3u);
            a[i][3] = mask2bf((mHi >> (shift + 8)) & 3u);
        }
        const int hp0 = 8 * step + lc;
        #pragma unroll
        for (int j = 0; j < 4; j++) {
            const int kp = kblk + 8 * j + lr;
            const uint32_t bh0 = smemu[O_UH + kp * UST + hp0];
            const uint32_t bh1 = smemu[O_UH + kp * UST + hp0 + 4];
            const uint32_t bl0 = smemu[O_UL + kp * UST + hp0];
            const uint32_t bl1 = smemu[O_UL + kp * UST + hp0 + 4];
            #pragma unroll
            for (int i = 0; i < 2; i++) {
                mma16bf(acc2[i][j], a[i], bh0, bh1);
                mma16bf(acc2[i][j], a[i], bl0, bl1);
            }
        }
    }

    // write hist_jac: jac = SLOPE*S[k] + RCOEF*acc2
    #pragma unroll
    for (int i = 0; i < 2; i++) {
        #pragma unroll
        for (int ci = 0; ci < 2; ci++) {
            const int r = nblk2 + 16 * i + 8 * ci + lr;
            float* hb2 = out + HIST_OFF + ((size_t)d * NTOT + n0 + r) * 64;
            #pragma unroll
            for (int j = 0; j < 4; j++) {
                const int col = kblk + 8 * j + 2 * lc;
                const float s0 = sf[O_S + col];
                const float s1 = sf[O_S + col + 1];
                float2 v = make_float2(fmaf(RCOEF, acc2[i][j][2 * ci],     SLOPE * s0),
                                       fmaf(RCOEF, acc2[i][j][2 * ci + 1], SLOPE * s1));
                *(float2*)(hb2 + col) = v;
            }
        }
    }

    __syncthreads();
    if (tid == 0) atomicAdd(&out[SUM_OFF + bb], sf[O_RED]);
}

extern "C" void kernel_launch(void* const* d_in, const int* in_sizes, int n_in,
                              void* d_out, int out_size) {
    const float* x  = (const float*)d_in[0];
    const float* W1 = (const float*)d_in[1];
    const float* b1 = (const float*)d_in[2];
    const float* W2 = (const float*)d_in[3];
    const float* b2 = (const float*)d_in[4];
    float* out = (float*)d_out;

    cudaFuncSetAttribute(fused_mma, cudaFuncAttributeMaxDynamicSharedMemorySize, SMEM_BYTES);

    zero_sum_kernel<<<1, Bb>>>(out);
    fused_mma<<<dim3(Dd, NTILES), 256, SMEM_BYTES>>>(x, W1, b1, W2, b2, out);
}

// round 17
// speedup vs baseline: 1.8373x; 1.8373x over previous
#include <cuda_runtime.h>
#include <cuda_fp16.h>
#include <math.h>
#include <stdint.h>

#define SLOPE 0.01f
constexpr float RCOEF = 1.0f - SLOPE;

// -------- problem constants --------
constexpr int Dd    = 32;
constexpr int Hh    = 128;
constexpr int Bb    = 64;
constexpr int Tt    = 514;
constexpr int TTt   = 512;
constexpr int NTOT  = Bb * TTt;          // 32768
constexpr int NTILE = 128;
constexpr int NTILES = NTOT / NTILE;     // 256

// output layout (reference return order, concatenated)
constexpr size_t RES_OFF  = 0;                        // (64,512,32)
constexpr size_t SUM_OFF  = (size_t)Bb * TTt * Dd;    // (64,)
constexpr size_t HIST_OFF = SUM_OFF + Bb;             // (32,32768,1,64)

// -------- shared offsets (u32 units) — 59 KB, 3 CTAs/SM (identical to R11) --------
constexpr int XWS = 36;                  // x-window row stride
constexpr int W1S = 68;                  // W1 row stride
constexpr int O_XW    = 0;                               // 130*36 = 4680 (reused as u_fp16 later)
constexpr int O_W1    = 4680;                            // 128*68 = 8704 (NOT overwritten)
constexpr int O_MASK  = 13384;                           // 128*4
constexpr int O_S     = 13896;                           // 64
constexpr int O_WLAST = 13960;                           // 128
constexpr int O_B1    = 14088;                           // 128
constexpr int O_W2    = 14216;                           // 128
constexpr int O_YY    = 14344;                           // 132
constexpr int O_RS    = 14476;                           // 128
constexpr int O_JS    = 14604;                           // 128
constexpr int O_RED   = 14732;                           // 4
constexpr int SMEM_U32 = 14736;
constexpr int SMEM_BYTES = SMEM_U32 * 4;                 // 58944

// u packed array (reusing dead x-window region): [k'=0..63][h_pair=0..63], stride 68
constexpr int O_UH = O_XW;    // 4352 <= 4680
constexpr int UST  = 68;

// CUTLASS-style fast 3xTF32 split: hi = truncate-to-tf32 (LOP3), lo = exact tail (FADD).
// lo is passed raw: tf32 HMMA reads only the top 19 bits, truncating for us.
__device__ __forceinline__ void split_fast(float v, uint32_t& hi, uint32_t& lo) {
    hi = __float_as_uint(v) & 0xFFFFE000u;
    lo = __float_as_uint(v - __uint_as_float(hi));
}

__device__ __forceinline__ void mma8(float* d, const uint32_t* a, uint32_t b0, uint32_t b1) {
    asm volatile(
        "mma.sync.aligned.m16n8k8.row.col.f32.tf32.tf32.f32 "
        "{%0,%1,%2,%3}, {%4,%5,%6,%7}, {%8,%9}, {%0,%1,%2,%3};"
        : "+f"(d[0]), "+f"(d[1]), "+f"(d[2]), "+f"(d[3])
        : "r"(a[0]), "r"(a[1]), "r"(a[2]), "r"(a[3]), "r"(b0), "r"(b1));
}
__device__ __forceinline__ void mma16h(float* d, const uint32_t* a, uint32_t b0, uint32_t b1) {
    asm volatile(
        "mma.sync.aligned.m16n8k16.row.col.f32.f16.f16.f32 "
        "{%0,%1,%2,%3}, {%4,%5,%6,%7}, {%8,%9}, {%0,%1,%2,%3};"
        : "+f"(d[0]), "+f"(d[1]), "+f"(d[2]), "+f"(d[3])
        : "r"(a[0]), "r"(a[1]), "r"(a[2]), "r"(a[3]), "r"(b0), "r"(b1));
}

// 2 mask bits -> fp16x2 {1.0|0.0, 1.0|0.0}; low half = lower h (bit0). 1.0h = 0x3C00.
__device__ __forceinline__ uint32_t mask2h(uint32_t p) {
    return (p & 1u) * 0x3C00u | (p & 2u) * 0x1E000000u;
}

__global__ void zero_sum_kernel(float* out) { out[SUM_OFF + threadIdx.x] = 0.0f; }

extern __shared__ uint32_t smemu[];

__global__ __launch_bounds__(256, 3)
void fused_mma(const float* __restrict__ x,  const float* __restrict__ W1,
               const float* __restrict__ b1, const float* __restrict__ W2,
               const float* __restrict__ b2, float* __restrict__ out)
{
    float* sf = (float*)smemu;
    const int tid  = threadIdx.x;
    const int lane = tid & 31;
    const int w    = tid >> 5;
    const int lr   = lane >> 2;   // 0..7
    const int lc   = lane & 3;    // 0..3

    const int d  = blockIdx.x;
    const int n0 = blockIdx.y * NTILE;
    const int bb = n0 / TTt;
    const int t0 = n0 % TTt;

    // ---------------- preamble ----------------
    {
        const float* W1g = W1 + (size_t)d * Hh * 65;
        for (int idx = tid; idx < Hh * 65; idx += 256) {
            int h = idx / 65;
            int k = idx - h * 65;
            float v = W1g[idx];
            if (k == 64) sf[O_WLAST + h] = v;
            else         sf[O_W1 + h * W1S + k] = v;
        }
        const float* xg = x + ((size_t)bb * Tt + t0) * Dd;
        for (int idx = tid; idx < 130 * 32; idx += 256) {
            int r = idx >> 5, c = idx & 31;
            float v = xg[idx];
            sf[O_XW + r * XWS + c] = v;
            if (c == d) sf[O_YY + r] = v;
        }
        if (tid < 128) {
            sf[O_B1 + tid] = b1[(size_t)d * Hh + tid];
            sf[O_W2 + tid] = W2[(size_t)d * Hh + tid];
            sf[O_RS + tid] = 0.0f;
            sf[O_JS + tid] = 0.0f;
        }
        if (tid == 0) sf[O_RED] = 0.0f;
    }
    __syncthreads();

    // colsums S[k] = sum_h w2[h]*W1[h][k]
    if (tid < 64) {
        float s = 0.0f;
        #pragma unroll 8
        for (int h = 0; h < Hh; h++)
            s = fmaf(sf[O_W2 + h], sf[O_W1 + h * W1S + tid], s);
        sf[O_S + tid] = s;
    }

    // ---------------- GEMM A: pre = XX @ W1[:, :64]^T (3xTF32), two 16-row passes --------
    const int nblk = (w & 3) * 32;
    const int hblk = (w >> 2) * 64;

    #pragma unroll 1
    for (int pass = 0; pass < 2; pass++) {
        const int rbase = nblk + 16 * pass;

        float acc[8][4];
        #pragma unroll
        for (int j = 0; j < 8; j++)
            #pragma unroll
            for (int q = 0; q < 4; q++) acc[j][q] = 0.0f;

        #pragma unroll 2
        for (int s = 0; s < 8; s++) {
            const int l  = s >> 2;
            const int c0 = ((8 * s) & 31) + lc;
            uint32_t ah[4], al[4];
            {
                int base = O_XW + (rbase + lr + l) * XWS + c0;
                split_fast(sf[base],               ah[0], al[0]);
                split_fast(sf[base + 8 * XWS],     ah[1], al[1]);
                split_fast(sf[base + 4],           ah[2], al[2]);
                split_fast(sf[base + 8 * XWS + 4], ah[3], al[3]);
            }
            #pragma unroll
            for (int j = 0; j < 8; j++) {
                int hb = O_W1 + (hblk + 8 * j + lr) * W1S + 8 * s + lc;
                uint32_t bh0, bl0, bh1, bl1;
                split_fast(sf[hb],     bh0, bl0);
                split_fast(sf[hb + 4], bh1, bl1);
                mma8(acc[j], ah, bh0, bh1);
                mma8(acc[j], ah, bl0, bl1);
                mma8(acc[j], al, bh0, bh1);
            }
        }

        // epilogue for this pass
        {
            float yyv[2], rp[2] = {0.0f, 0.0f}, jp[2] = {0.0f, 0.0f};
            uint32_t mm0[2] = {0u, 0u}, mm1[2] = {0u, 0u};
            #pragma unroll
            for (int ci = 0; ci < 2; ci++)
                yyv[ci] = sf[O_YY + rbase + 8 * ci + lr + 2];

            #pragma unroll
            for (int j = 0; j < 8; j++) {
                #pragma unroll
                for (int cj = 0; cj < 2; cj++) {
                    const int h = hblk + 8 * j + 2 * lc + cj;
                    const float wl = sf[O_WLAST + h];
                    const float bv = sf[O_B1 + h];
                    const float w2 = sf[O_W2 + h];
                    const uint32_t bitv = 1u << (8 * (j & 3) + 2 * lc + cj);
                    #pragma unroll
                    for (int ci = 0; ci < 2; ci++) {
                        float pre = fmaf(yyv[ci], wl, acc[j][2 * ci + cj]) + bv;
                        float gv = (pre >= 0.0f) ? w2 : SLOPE * w2;
                        rp[ci] = fmaf(pre, gv, rp[ci]);
                        jp[ci] = fmaf(gv, wl, jp[ci]);
                        uint32_t bit = (pre >= 0.0f) ? bitv : 0u;
                        if (j < 4) mm0[ci] |= bit; else mm1[ci] |= bit;
                    }
                }
            }
            #pragma unroll
            for (int ci = 0; ci < 2; ci++) {
                const int row = rbase + 8 * ci + lr;
                uint32_t m0 = mm0[ci], m1 = mm1[ci];
                float rpv = rp[ci], jpv = jp[ci];
                m0 |= __shfl_xor_sync(0xffffffffu, m0, 1);
                m0 |= __shfl_xor_sync(0xffffffffu, m0, 2);
                m1 |= __shfl_xor_sync(0xffffffffu, m1, 1);
                m1 |= __shfl_xor_sync(0xffffffffu, m1, 2);
                rpv += __shfl_xor_sync(0xffffffffu, rpv, 1);
                rpv += __shfl_xor_sync(0xffffffffu, rpv, 2);
                jpv += __shfl_xor_sync(0xffffffffu, jpv, 1);
                jpv += __shfl_xor_sync(0xffffffffu, jpv, 2);
                if (lc == 0) {
                    smemu[O_MASK + row * 4 + (hblk >> 5)]     = m0;
                    smemu[O_MASK + row * 4 + (hblk >> 5) + 1] = m1;
                    atomicAdd(&sf[O_RS + row], rpv);
                    atomicAdd(&sf[O_JS + row], jpv);
                }
            }
        }
    }
    __syncthreads();

    // residual + logdet outputs
    if (tid < 128) {
        const int n = tid;
        out[RES_OFF + ((size_t)(bb * TTt + t0 + n)) * Dd + d] = sf[O_RS + n] + __ldg(&b2[d]);
        float ls = logf(fabsf(sf[O_JS + n]));
        #pragma unroll
        for (int o = 16; o; o >>= 1) ls += __shfl_down_sync(0xffffffffu, ls, o);
        if (lane == 0) atomicAdd(&sf[O_RED], ls);
    }

    // ---------------- build u = w2 .* W1 as packed fp16 (single term) -------------------
    // writes into the dead x-window region; W1 stays intact (no overwrite hazard)
    #pragma unroll 4
    for (int t = 0; t < 16; t++) {
        const int idx = tid + 256 * t;          // 0..4095
        const int k = idx >> 6, hp = idx & 63;
        const int h0 = 2 * hp, h1 = 2 * hp + 1;
        const float u0 = sf[O_W1 + h0 * W1S + k] * sf[O_W2 + h0];
        const float u1 = sf[O_W1 + h1 * W1S + k] * sf[O_W2 + h1];
        __half2 p = __floats2half2_rn(u0, u1);  // .x (low) = even h
        smemu[O_UH + k * UST + hp] = *(uint32_t*)&p;
    }
    __syncthreads();

    // ---------------- GEMM B: jac = SLOPE*S + RCOEF*(mask @ u)  (fp16, k16, 1 term) -----
    const int nblk2 = (w & 3) * 32;
    const int kblk  = (w >> 2) * 32;

    float acc2[2][4][4];
    #pragma unroll
    for (int i = 0; i < 2; i++)
        #pragma unroll
        for (int j = 0; j < 4; j++)
            #pragma unroll
            for (int q = 0; q < 4; q++) acc2[i][j][q] = 0.0f;

    #pragma unroll 2
    for (int step = 0; step < 8; step++) {
        const int mw    = step >> 1;
        const int shift = (step & 1) * 16 + 2 * lc;
        uint32_t a[2][4];
        #pragma unroll
        for (int i = 0; i < 2; i++) {
            const uint32_t mLo = smemu[O_MASK + (nblk2 + 16 * i + lr) * 4 + mw];
            const uint32_t mHi = smemu[O_MASK + (nblk2 + 16 * i + lr + 8) * 4 + mw];
            a[i][0] = mask2h((mLo >> shift) & 3u);
            a[i][1] = mask2h((mHi >> shift) & 3u);
            a[i][2] = mask2h((mLo >> (shift + 8)) & 3u);
            a[i][3] = mask2h((mHi >> (shift + 8)) & 3u);
        }
        const int hp0 = 8 * step + lc;
        #pragma unroll
        for (int j = 0; j < 4; j++) {
            const int kp = kblk + 8 * j + lr;
            const uint32_t bh0 = smemu[O_UH + kp * UST + hp0];
            const uint32_t bh1 = smemu[O_UH + kp * UST + hp0 + 4];
            #pragma unroll
            for (int i = 0; i < 2; i++)
                mma16h(acc2[i][j], a[i], bh0, bh1);
        }
    }

    // write hist_jac: jac = SLOPE*S[k] + RCOEF*acc2
    #pragma unroll
    for (int i = 0; i < 2; i++) {
        #pragma unroll
        for (int ci = 0; ci < 2; ci++) {
            const int r = nblk2 + 16 * i + 8 * ci + lr;
            float* hb2 = out + HIST_OFF + ((size_t)d * NTOT + n0 + r) * 64;
            #pragma unroll
            for (int j = 0; j < 4; j++) {
                const int col = kblk + 8 * j + 2 * lc;
                const float s0 = sf[O_S + col];
                const float s1 = sf[O_S + col + 1];
                float2 v = make_float2(fmaf(RCOEF, acc2[i][j][2 * ci],     SLOPE * s0),
                                       fmaf(RCOEF, acc2[i][j][2 * ci + 1], SLOPE * s1));
                *(float2*)(hb2 + col) = v;
            }
        }
    }

    __syncthreads();
    if (tid == 0) atomicAdd(&out[SUM_OFF + bb], sf[O_RED]);
}

extern "C" void kernel_launch(void* const* d_in, const int* in_sizes, int n_in,
                              void* d_out, int out_size) {
    const float* x  = (const float*)d_in[0];
    const float* W1 = (const float*)d_in[1];
    const float* b1 = (const float*)d_in[2];
    const float* W2 = (const float*)d_in[3];
    const float* b2 = (const float*)d_in[4];
    float* out = (float*)d_out;

    cudaFuncSetAttribute(fused_mma, cudaFuncAttributeMaxDynamicSharedMemorySize, SMEM_BYTES);

    zero_sum_kernel<<<1, Bb>>>(out);
    fused_mma<<<dim3(Dd, NTILES), 256, SMEM_BYTES>>>(x, W1, b1, W2, b2, out);
}